// round 10
// baseline (speedup 1.0000x reference)
#include <cuda_runtime.h>

#define B_   2048
#define T_   128
#define S_   256
#define H_   64
#define E_   32
#define V_   29
#define G4   256   // 4*H
#define ES   68    // enc SMEM row stride; halves at +0 and +34
#define NT   768

typedef unsigned long long ull;

struct __align__(16) Smem {
    float enc[S_ * ES];        // 69632 B
    float gate_emb[V_ * G4];   // 29696 B : W_ih[:, :32]@emb[v] + b_ih + b_hh
    float fcW[V_ * 128 + 32];
    float embS[V_ * E_];       // prologue only
    float part[16 * 64];
    float scores[S_];
    float gpart[3 * G4];       // [0:256)=ctx-lo, [256:512)=ctx-hi, [512:768)=W_hh@h
    float bias[G4];            // prologue only
    float comb[128];           // [0:64)=h [64:128)=ctx  (P6 input, stable in phase A)
    float hdup[72];            // h halves at 0 / 40 (bank offset)
    float cdup[72];            // ctx halves at 0 / 40
    float fcb[32];
    float redsum[16];
    int   ytok[T_];
};

__device__ __forceinline__ ull pack2(float lo, float hi) {
    ull r; asm("mov.b64 %0, {%1, %2};" : "=l"(r) : "f"(lo), "f"(hi)); return r;
}
__device__ __forceinline__ ull fma2(ull a, ull b, ull c) {
    ull d; asm("fma.rn.f32x2 %0, %1, %2, %3;" : "=l"(d) : "l"(a), "l"(b), "l"(c));
    return d;
}
__device__ __forceinline__ float2 unpack2(ull v) {
    float lo, hi; asm("mov.b64 {%0, %1}, %2;" : "=f"(lo), "=f"(hi) : "l"(v));
    return make_float2(lo, hi);
}
__device__ __forceinline__ float sigmoid_(float z) {
    return 1.0f / (1.0f + __expf(-z));
}
__device__ __forceinline__ float tanh_(float x) {
    return 1.0f - 2.0f / (__expf(2.0f * x) + 1.0f);
}

extern "C" __global__ void __launch_bounds__(NT, 1)
decoder_persist_kernel(const int* __restrict__ y,
                       const float* __restrict__ h0,
                       const float* __restrict__ c0,
                       const float* __restrict__ enc_g,
                       const float* __restrict__ embt,
                       const float* __restrict__ Wih,
                       const float* __restrict__ Whh,
                       const float* __restrict__ bih,
                       const float* __restrict__ bhh,
                       const float* __restrict__ fcWg,
                       const float* __restrict__ fcbg,
                       float* __restrict__ out)
{
    extern __shared__ __align__(16) char smem_raw[];
    Smem& sm = *reinterpret_cast<Smem*>(smem_raw);
    const int tid  = threadIdx.x;
    const int b    = blockIdx.x;
    const int lane = tid & 31;
    const int wrp  = tid >> 5;
    const int r    = tid >> 1;    // P1 score row (tid<512)
    const int half = tid & 1;
    const int rc   = tid & 255;   // P4c gate row (tid<512)
    const int gsl  = tid >> 8;    // 0: ctx[0:32), 1: ctx[32:64)  (tid<512)
    const int rh   = tid - 512;   // P4h gate row (tid>=512)

    // ---- stage enc (mid-row pad), constants ----
    {
        const float2* eb = reinterpret_cast<const float2*>(enc_g + (size_t)b * (S_ * H_));
        for (int i2 = tid; i2 < (S_ * H_) / 2; i2 += NT) {
            float2 v = eb[i2];
            int s  = i2 >> 5;
            int h2 = (i2 & 31) << 1;
            int dst = s * ES + h2 + ((h2 >= 32) ? 2 : 0);
            *reinterpret_cast<float2*>(&sm.enc[dst]) = v;
        }
    }
    for (int i = tid; i < V_ * 128; i += NT) sm.fcW[i] = fcWg[i];
    for (int i = tid; i < V_ * E_;  i += NT) sm.embS[i] = embt[i];
    if (tid < G4) sm.bias[tid] = bih[tid] + bhh[tid];
    if (tid < V_) sm.fcb[tid]  = fcbg[tid];
    if (tid < T_) sm.ytok[tid] = y[b * T_ + tid];
    float creg = 0.0f;
    if (tid < H_) {
        float hv = h0[b * H_ + tid];
        sm.comb[tid] = hv;
        sm.hdup[tid + ((tid >> 5) << 3)] = hv;   // halves at 0 / 40
        creg = c0[b * H_ + tid];
    }
    __syncthreads();

    // ---- prologue: gate_emb[v][r] = W_ih[r, :32].emb[v] + bias[r] ----
    if (tid < 512) {
        float4 we[4];
        const float4* wg = reinterpret_cast<const float4*>(Wih + r * 96 + 16 * half);
        #pragma unroll
        for (int k = 0; k < 4; k++) we[k] = wg[k];
        float brow = sm.bias[r];
        for (int v = 0; v < V_; v++) {
            const float4* em = reinterpret_cast<const float4*>(sm.embS + v * E_ + 16 * half);
            float a = 0.f;
            #pragma unroll
            for (int k = 0; k < 4; k++) {
                float4 e = em[k];
                a += we[k].x*e.x + we[k].y*e.y + we[k].z*e.z + we[k].w*e.w;
            }
            a += __shfl_xor_sync(0xffffffffu, a, 1);
            if (half == 0) sm.gate_emb[v * G4 + r] = a + brow;
        }
    }

    // ---- persistent weights ----
    // tid<512:  8 ull = W_ih[rc, 32+32*gsl : 32+32*gsl+32)   (ctx slice)
    // tid>=512: 16 ull = W_hh[rh, 0:64)
    ull wc2[8];
    ull wh2[16];
    if (tid < 512) {
        const float4* wp = reinterpret_cast<const float4*>(Wih + rc * 96 + 32 + 32 * gsl);
        #pragma unroll
        for (int k = 0; k < 8; k++) {
            float4 v = wp[k];
            wc2[k] = pack2(v.x, v.y);
            // pack z,w into odd slots via second array half:
        }
        // repack cleanly: wc2 holds 8 ull = 16 floats? Need 32 floats -> 16 ull.
    }
    // NOTE: 32 floats need 16 ull; use wh2 as storage for tid<512 too.
    if (tid < 512) {
        const float4* wp = reinterpret_cast<const float4*>(Wih + rc * 96 + 32 + 32 * gsl);
        #pragma unroll
        for (int k = 0; k < 8; k++) {
            float4 v = wp[k];
            wh2[2*k]   = pack2(v.x, v.y);
            wh2[2*k+1] = pack2(v.z, v.w);
        }
    } else {
        const float4* wp = reinterpret_cast<const float4*>(Whh + rh * 64);
        #pragma unroll
        for (int k = 0; k < 16; k++) {
            float4 v = wp[k];
            wh2[2*(k & 7) + ((k >> 3) ? 0 : 0)] = wh2[2*(k & 7)];  // placeholder fix below
        }
    }
    // The above got tangled; do it simply: wh2[16] holds 32 floats. For tid>=512
    // we need 64 floats -> reuse wc2[8] as the upper 16 floats... Clean final:
    //   tid<512 : wh2[0..15] = W_ih ctx slice (32 floats)
    //   tid>=512: wh2[0..15] = W_hh[rh, 0:32), wc2[0..7] = W_hh[rh,32:48)?? not enough.
    // -> declare wx2[8] extra for tid>=512 lower need. Handled below properly.
    ull wx2[8];
    if (tid >= 512) {
        const float4* wp = reinterpret_cast<const float4*>(Whh + rh * 64);
        #pragma unroll
        for (int k = 0; k < 8; k++) {
            float4 v = wp[k];
            wh2[2*k]   = pack2(v.x, v.y);
            wh2[2*k+1] = pack2(v.z, v.w);
        }
        #pragma unroll
        for (int k = 0; k < 4; k++) {
            float4 v0 = wp[8 + 2*k], v1 = wp[9 + 2*k];
            wc2[2*k]   = pack2(v0.x, v0.y);
            wc2[2*k+1] = pack2(v0.z, v0.w);
            wx2[2*k]   = pack2(v1.x, v1.y);
            wx2[2*k+1] = pack2(v1.z, v1.w);
        }
    }
    __syncthreads();

    float* outp = out + (size_t)b * T_ * V_;

    for (int t = 0; t < T_; t++) {
        // ======== Phase A ========
        if (tid < 512) {
            // P1: e_s = exp(enc[s,:].h)  (R9-verified code)
            const ull* ep = reinterpret_cast<const ull*>(sm.enc + r * ES + half * 34);
            const ull* hp = reinterpret_cast<const ull*>(sm.hdup + half * 40);
            ull a0 = 0ull, a1 = 0ull;
            #pragma unroll
            for (int k = 0; k < 16; k += 2) {
                a0 = fma2(ep[k],     hp[k],     a0);
                a1 = fma2(ep[k + 1], hp[k + 1], a1);
            }
            float2 fa = unpack2(a0), fb = unpack2(a1);
            float sc = (fa.x + fa.y) + (fb.x + fb.y);
            sc += __shfl_xor_sync(0xffffffffu, sc, 1);
            float e = __expf(sc);
            if (half == 0) sm.scores[r] = e;
            float su = e;
            #pragma unroll
            for (int o = 16; o > 1; o >>= 1)
                su += __shfl_xor_sync(0xffffffffu, su, o);
            if (lane == 0) sm.redsum[wrp] = su;   // warp's 16 distinct scores
        } else {
            // P4h: gpart[512+rh] = W_hh[rh,:] . h_{t-1}
            {
                const float4* v0 = reinterpret_cast<const float4*>(sm.hdup);        // h[0:32)
                const float4* v1 = reinterpret_cast<const float4*>(sm.hdup + 40);   // h[32:64)
                ull a0 = 0ull, a1 = 0ull;
                #pragma unroll
                for (int k = 0; k < 8; k++) {
                    float4 xv = v0[k];
                    a0 = fma2(wh2[2*k],   pack2(xv.x, xv.y), a0);
                    a1 = fma2(wh2[2*k+1], pack2(xv.z, xv.w), a1);
                }
                #pragma unroll
                for (int k = 0; k < 4; k++) {
                    float4 xv = v1[2*k];
                    float4 yv = v1[2*k + 1];
                    a0 = fma2(wc2[2*k],   pack2(xv.x, xv.y), a0);
                    a1 = fma2(wc2[2*k+1], pack2(xv.z, xv.w), a1);
                    a0 = fma2(wx2[2*k],   pack2(yv.x, yv.y), a0);
                    a1 = fma2(wx2[2*k+1], pack2(yv.z, yv.w), a1);
                }
                float2 fa = unpack2(a0), fb = unpack2(a1);
                sm.gpart[512 + rh] = (fa.x + fa.y) + (fb.x + fb.y);
            }
            // P6 (pipelined): logits for step t-1 from comb = [h_{t-1}, ctx_{t-1}]
            if (t > 0) {
                int vv = rh >> 3;          // 0..31
                int p  = lane & 7;         // 8 threads per vocab row
                float acc = 0.0f;
                if (vv < V_) {
                    const float4* fw = reinterpret_cast<const float4*>(sm.fcW + vv * 128 + p * 16);
                    const float4* cb = reinterpret_cast<const float4*>(sm.comb + p * 16);
                    #pragma unroll
                    for (int k = 0; k < 4; k++) {
                        float4 w = fw[k], c = cb[k];
                        acc += w.x*c.x + w.y*c.y + w.z*c.z + w.w*c.w;
                    }
                }
                #pragma unroll
                for (int o = 4; o; o >>= 1)
                    acc += __shfl_xor_sync(0xffffffffu, acc, o);
                if (p == 0 && vv < V_)
                    outp[(t - 1) * V_ + vv] = acc + sm.fcb[vv];
            }
        }
        __syncthreads();  // bar1

        // ======== Phase B: P3 context partials (warps 0-15, R9-verified) ========
        if (wrp < 16) {
            const int sbase = wrp * 16;
            const float*  ebase = sm.enc + sbase * ES + 2 * lane + ((lane >> 4) & 1) * 2;
            const float4* sp = reinterpret_cast<const float4*>(sm.scores + sbase);
            float ax = 0.f, ay = 0.f;
            #pragma unroll
            for (int c = 0; c < 4; c++) {
                float4 sv = sp[c];
                float2 e0 = *reinterpret_cast<const float2*>(ebase + (4*c + 0) * ES);
                float2 e1 = *reinterpret_cast<const float2*>(ebase + (4*c + 1) * ES);
                float2 e2 = *reinterpret_cast<const float2*>(ebase + (4*c + 2) * ES);
                float2 e3 = *reinterpret_cast<const float2*>(ebase + (4*c + 3) * ES);
                ax += sv.x * e0.x; ay += sv.x * e0.y;
                ax += sv.y * e1.x; ay += sv.y * e1.y;
                ax += sv.z * e2.x; ay += sv.z * e2.y;
                ax += sv.w * e3.x; ay += sv.w * e3.y;
            }
            *reinterpret_cast<float2*>(&sm.part[wrp * 64 + 2 * lane]) = make_float2(ax, ay);
        }
        __syncthreads();  // bar2

        // ======== Phase C: ctx reduce + normalize ========
        if (tid < H_) {
            float ssum = 0.f;
            #pragma unroll
            for (int k = 0; k < 16; k++) ssum += sm.redsum[k];
            float inv = 1.0f / ssum;
            float ctx = 0.f;
            #pragma unroll
            for (int q = 0; q < 16; q++) ctx += sm.part[q * 64 + tid];
            ctx *= inv;
            sm.comb[H_ + tid] = ctx;
            sm.cdup[tid + ((tid >> 5) << 3)] = ctx;   // halves at 0 / 40
        }
        __syncthreads();  // bar3

        // ======== Phase D: P4c ctx slices (warps 0-15) ========
        if (tid < 512) {
            const float4* vp = reinterpret_cast<const float4*>(sm.cdup + 40 * gsl);
            ull a0 = 0ull, a1 = 0ull;
            #pragma unroll
            for (int k = 0; k < 8; k++) {
                float4 xv = vp[k];
                a0 = fma2(wh2[2*k],   pack2(xv.x, xv.y), a0);
                a1 = fma2(wh2[2*k+1], pack2(xv.z, xv.w), a1);
            }
            float2 fa = unpack2(a0), fb = unpack2(a1);
            sm.gpart[gsl * G4 + rc] = (fa.x + fa.y) + (fb.x + fb.y);
        }
        __syncthreads();  // bar4

        // ======== Phase E: P5 combine + LSTM cell (i,f,g,o) ========
        if (tid < H_) {
            int tok = sm.ytok[t];
            const float* ge = sm.gate_emb + tok * G4;
            float g[4];
            #pragma unroll
            for (int gi = 0; gi < 4; gi++) {
                int row = gi * 64 + tid;
                g[gi] = sm.gpart[row] + sm.gpart[G4 + row] + sm.gpart[2*G4 + row]
                      + ge[row];
            }
            creg = sigmoid_(g[1]) * creg + sigmoid_(g[0]) * tanh_(g[2]);
            float hnew = sigmoid_(g[3]) * tanh_(creg);
            sm.comb[tid] = hnew;
            sm.hdup[tid + ((tid >> 5) << 3)] = hnew;
        }
        __syncthreads();  // bar5 (phase A of t+1 reads comb/hdup)
    }

    // ---- epilogue: logits for the final step (t = T-1) ----
    if (tid >= 512) {
        int vv = rh >> 3;
        int p  = lane & 7;
        float acc = 0.0f;
        if (vv < V_) {
            const float4* fw = reinterpret_cast<const float4*>(sm.fcW + vv * 128 + p * 16);
            const float4* cb = reinterpret_cast<const float4*>(sm.comb + p * 16);
            #pragma unroll
            for (int k = 0; k < 4; k++) {
                float4 w = fw[k], c = cb[k];
                acc += w.x*c.x + w.y*c.y + w.z*c.z + w.w*c.w;
            }
        }
        #pragma unroll
        for (int o = 4; o; o >>= 1)
            acc += __shfl_xor_sync(0xffffffffu, acc, o);
        if (p == 0 && vv < V_)
            outp[(T_ - 1) * V_ + vv] = acc + sm.fcb[vv];
    }
}

extern "C" void kernel_launch(void* const* d_in, const int* in_sizes, int n_in,
                              void* d_out, int out_size) {
    const int*   y    = (const int*)d_in[0];
    const float* h0   = (const float*)d_in[1];
    const float* c0   = (const float*)d_in[2];
    const float* enc  = (const float*)d_in[3];
    const float* emb  = (const float*)d_in[4];
    const float* Wih  = (const float*)d_in[5];
    const float* Whh  = (const float*)d_in[6];
    const float* bih  = (const float*)d_in[7];
    const float* bhh  = (const float*)d_in[8];
    const float* fcW  = (const float*)d_in[9];
    const float* fcb  = (const float*)d_in[10];
    float* out = (float*)d_out;

    size_t smem = sizeof(Smem);
    cudaFuncSetAttribute(decoder_persist_kernel,
                         cudaFuncAttributeMaxDynamicSharedMemorySize, (int)smem);
    decoder_persist_kernel<<<B_, NT, smem>>>(y, h0, c0, enc, emb,
                                             Wih, Whh, bih, bhh, fcW, fcb, out);
}

// round 11
// speedup vs baseline: 1.1246x; 1.1246x over previous
#include <cuda_runtime.h>

#define B_   2048
#define T_   128
#define S_   256
#define H_   64
#define E_   32
#define V_   29
#define G4   256   // 4*H

typedef unsigned long long ull;

// enc layout: stride 64, XOR-swizzled: logical (s, w) lives at word
//   s*64 + (w ^ ((4*s) & 63))
// P1 (row reads, LDS.128) and P3 (column reads, LDS.32) both at bank floor.

struct __align__(16) Smem {
    float enc[S_ * 64];       // 65536 B
    float fcW[32 * 128];      // 16384 B (rows 29..31 unused)
    float embS[V_ * E_];      // emb table
    float scores[S_];         // e_s (no max subtraction; |score| bounded)
    float part[16 * 64];      // context partials [q][hd]
    float gates[G4];
    float bias[G4];           // b_ih + b_hh
    float comb[128];          // [0:64)=h  [64:128)=ctx  (fc input)
    float hdup[72];           // h halves at 0 / 40 (bank offset)
    float xbuf[96];           // [0:32)=emb_t  [32:96)=ctx (lstm input)
    float fcb[32];
    float redsum[16];
    int   ytok[T_];
};

__device__ __forceinline__ ull pack2(float lo, float hi) {
    ull r; asm("mov.b64 %0, {%1, %2};" : "=l"(r) : "f"(lo), "f"(hi)); return r;
}
__device__ __forceinline__ ull fma2(ull a, ull b, ull c) {
    ull d; asm("fma.rn.f32x2 %0, %1, %2, %3;" : "=l"(d) : "l"(a), "l"(b), "l"(c));
    return d;
}
__device__ __forceinline__ float2 unpack2(ull v) {
    float lo, hi; asm("mov.b64 {%0, %1}, %2;" : "=f"(lo), "=f"(hi) : "l"(v));
    return make_float2(lo, hi);
}
__device__ __forceinline__ float sigmoid_(float z) {
    return 1.0f / (1.0f + __expf(-z));
}
__device__ __forceinline__ float tanh_(float x) {
    return 1.0f - 2.0f / (__expf(2.0f * x) + 1.0f);
}

extern "C" __global__ void __launch_bounds__(512, 1)
decoder_persist_kernel(const int* __restrict__ y,
                       const float* __restrict__ h0,
                       const float* __restrict__ c0,
                       const float* __restrict__ enc_g,
                       const float* __restrict__ embt,
                       const float* __restrict__ Wih,
                       const float* __restrict__ Whh,
                       const float* __restrict__ bih,
                       const float* __restrict__ bhh,
                       const float* __restrict__ fcWg,
                       const float* __restrict__ fcbg,
                       float* __restrict__ out)
{
    extern __shared__ __align__(16) char smem_raw[];
    Smem& sm = *reinterpret_cast<Smem*>(smem_raw);
    const int tid  = threadIdx.x;
    const int b    = blockIdx.x;
    const int lane = tid & 31;
    const int wrp  = tid >> 5;
    const int r    = tid >> 1;   // gate/score row
    const int half = tid & 1;

    // ---- per-thread gate weights, packed f32x2 (80 regs) — R3 verbatim ----
    ull wih2[24], whh2[16];
    {
        const float4* p = reinterpret_cast<const float4*>(Wih + 48 * tid);
        #pragma unroll
        for (int k = 0; k < 12; k++) {
            float4 v = p[k];
            wih2[2*k]   = pack2(v.x, v.y);
            wih2[2*k+1] = pack2(v.z, v.w);
        }
        const float4* q = reinterpret_cast<const float4*>(Whh + 32 * tid);
        #pragma unroll
        for (int k = 0; k < 8; k++) {
            float4 v = q[k];
            whh2[2*k]   = pack2(v.x, v.y);
            whh2[2*k+1] = pack2(v.z, v.w);
        }
    }

    // ---- stage enc with XOR swizzle + constants ----
    {
        const float2* eb = reinterpret_cast<const float2*>(enc_g + (size_t)b * (S_ * H_));
        for (int i2 = tid; i2 < (S_ * H_) / 2; i2 += 512) {
            float2 v = eb[i2];
            int s = i2 >> 5;
            int w = (i2 & 31) << 1;                  // 0,2,...,62
            int dst = (s << 6) + (w ^ ((4 * s) & 63));
            *reinterpret_cast<float2*>(&sm.enc[dst]) = v;
        }
    }
    for (int i = tid; i < V_ * 128; i += 512) sm.fcW[i] = fcWg[i];
    for (int i = tid; i < V_ * E_;  i += 512) sm.embS[i] = embt[i];
    if (tid < G4) sm.bias[tid] = bih[tid] + bhh[tid];
    if (tid < V_) sm.fcb[tid]  = fcbg[tid];
    if (tid < T_) sm.ytok[tid] = y[b * T_ + tid];
    float creg = 0.0f;
    if (tid < H_) {
        float hv = h0[b * H_ + tid];
        sm.comb[tid] = hv;
        sm.hdup[tid + ((tid >> 5) << 3)] = hv;   // halves at 0 / 40
        creg = c0[b * H_ + tid];
    }
    __syncthreads();

    float* outp = out + (size_t)b * T_ * V_;

    for (int t = 0; t < T_; t++) {
        // ---- P1: e_s = exp(enc[s,:].h)  (2 threads per s, swizzled LDS.128) ----
        {
            const float4* hp4 = reinterpret_cast<const float4*>(sm.hdup + 40 * half);
            const int rot  = (4 * r) & 63;
            const int rowb = r << 6;
            ull a0 = 0ull, a1 = 0ull;
            #pragma unroll
            for (int j = 0; j < 8; j++) {
                int pw = rowb + (((half << 5) + (j << 2)) ^ rot);
                float4 ev = *reinterpret_cast<const float4*>(sm.enc + pw);
                float4 hv = hp4[j];
                a0 = fma2(pack2(ev.x, ev.y), pack2(hv.x, hv.y), a0);
                a1 = fma2(pack2(ev.z, ev.w), pack2(hv.z, hv.w), a1);
            }
            float2 fa = unpack2(a0), fb = unpack2(a1);
            float sc = (fa.x + fa.y) + (fb.x + fb.y);
            sc += __shfl_xor_sync(0xffffffffu, sc, 1);
            float e = __expf(sc);            // |sc| bounded: no overflow
            if (half == 0) sm.scores[r] = e;
            float su = e;
            #pragma unroll
            for (int o = 16; o > 1; o >>= 1)
                su += __shfl_xor_sync(0xffffffffu, su, o);
            // lane 0 = sum over even lanes = warp's 16 distinct scores, once each
            if (lane == 0) sm.redsum[wrp] = su;
        }
        __syncthreads();  // bar1: scores, redsum

        // ---- P3: context partials; lane l owns hd = l and l+32 (conflict-free) ----
        {
            const int sbase = wrp * 16;
            float sc16[16];
            {
                const float4* sp = reinterpret_cast<const float4*>(sm.scores + sbase);
                #pragma unroll
                for (int k = 0; k < 4; k++) {
                    float4 v = sp[k];
                    sc16[4*k] = v.x; sc16[4*k+1] = v.y; sc16[4*k+2] = v.z; sc16[4*k+3] = v.w;
                }
            }
            float ax = 0.f, ay = 0.f;
            #pragma unroll
            for (int i = 0; i < 16; i++) {
                int s = sbase + i;
                const float* rowp = sm.enc + (s << 6);
                int w1 = lane ^ ((4 * s) & 63);
                ax += sc16[i] * rowp[w1];
                ay += sc16[i] * rowp[w1 ^ 32];
            }
            sm.part[wrp * 64 + lane]      = ax;   // hd = lane
            sm.part[wrp * 64 + lane + 32] = ay;   // hd = lane + 32
        }
        __syncthreads();  // bar2: part

        // ---- ctx reduce + normalize; idle threads fetch embedding ----
        if (tid < H_) {
            float ssum = 0.f;
            #pragma unroll
            for (int k = 0; k < 16; k++) ssum += sm.redsum[k];
            float inv = 1.0f / ssum;
            float ctx = 0.f;
            #pragma unroll
            for (int q = 0; q < 16; q++) ctx += sm.part[q * 64 + tid];
            ctx *= inv;
            sm.xbuf[E_ + tid] = ctx;
            sm.comb[H_ + tid] = ctx;
        } else if (tid < 96) {
            int j = tid - 64;
            sm.xbuf[j] = sm.embS[sm.ytok[t] * E_ + j];
        }
        __syncthreads();  // bar3: xbuf, comb[64:]

        // ---- P4: gates (2 threads/row, f32x2) — R3 verbatim ----
        {
            const ull* xp = reinterpret_cast<const ull*>(sm.xbuf + half * 48);
            const ull* hp = reinterpret_cast<const ull*>(sm.hdup + half * 40);
            ull a0 = 0ull, a1 = 0ull;
            #pragma unroll
            for (int k = 0; k < 24; k += 2) {
                a0 = fma2(wih2[k],     xp[k],     a0);
                a1 = fma2(wih2[k + 1], xp[k + 1], a1);
            }
            #pragma unroll
            for (int k = 0; k < 16; k += 2) {
                a0 = fma2(whh2[k],     hp[k],     a0);
                a1 = fma2(whh2[k + 1], hp[k + 1], a1);
            }
            float2 fa = unpack2(a0), fb = unpack2(a1);
            float g = (fa.x + fa.y) + (fb.x + fb.y);
            g += __shfl_xor_sync(0xffffffffu, g, 1);
            if (half == 0) sm.gates[r] = g + sm.bias[r];
        }
        __syncthreads();  // bar4: gates

        // ---- P5: LSTM cell (torch order i,f,g,o) ----
        if (tid < H_) {
            float ig = sm.gates[tid];
            float fg = sm.gates[H_ + tid];
            float gg = sm.gates[2 * H_ + tid];
            float og = sm.gates[3 * H_ + tid];
            creg = sigmoid_(fg) * creg + sigmoid_(ig) * tanh_(gg);
            float hnew = sigmoid_(og) * tanh_(creg);
            sm.comb[tid] = hnew;
            sm.hdup[tid + ((tid >> 5) << 3)] = hnew;
        }
        __syncthreads();  // bar5: h

        // ---- P6: logits (16 threads per vocab row) — R3 verbatim ----
        {
            int v = tid >> 4, p = tid & 15;
            float acc = 0.0f;
            if (v < V_) {
                const float4* fw = reinterpret_cast<const float4*>(sm.fcW + v * 128 + p * 8);
                const float4* cb = reinterpret_cast<const float4*>(sm.comb + p * 8);
                float4 w0 = fw[0], w1 = fw[1];
                float4 c0v = cb[0], c1v = cb[1];
                acc = w0.x*c0v.x + w0.y*c0v.y + w0.z*c0v.z + w0.w*c0v.w
                    + w1.x*c1v.x + w1.y*c1v.y + w1.z*c1v.z + w1.w*c1v.w;
            }
            #pragma unroll
            for (int o = 8; o; o >>= 1)
                acc += __shfl_xor_sync(0xffffffffu, acc, o);
            if (p == 0 && v < V_)
                outp[t * V_ + v] = acc + sm.fcb[v];
        }
        // no trailing barrier: next-step writes to comb/hdup occur only after
        // bar3/bar5 of step t+1, which transitively require all warps past P6.
    }
}

extern "C" void kernel_launch(void* const* d_in, const int* in_sizes, int n_in,
                              void* d_out, int out_size) {
    const int*   y    = (const int*)d_in[0];
    const float* h0   = (const float*)d_in[1];
    const float* c0   = (const float*)d_in[2];
    const float* enc  = (const float*)d_in[3];
    const float* emb  = (const float*)d_in[4];
    const float* Wih  = (const float*)d_in[5];
    const float* Whh  = (const float*)d_in[6];
    const float* bih  = (const float*)d_in[7];
    const float* bhh  = (const float*)d_in[8];
    const float* fcW  = (const float*)d_in[9];
    const float* fcb  = (const float*)d_in[10];
    float* out = (float*)d_out;

    size_t smem = sizeof(Smem);
    cudaFuncSetAttribute(decoder_persist_kernel,
                         cudaFuncAttributeMaxDynamicSharedMemorySize, (int)smem);
    decoder_persist_kernel<<<B_, 512, smem>>>(y, h0, c0, enc, emb,
                                              Wih, Whh, bih, bhh, fcW, fcb, out);
}

// round 14
// speedup vs baseline: 1.1619x; 1.0332x over previous
#include <cuda_runtime.h>

#define B_   2048
#define T_   128
#define S_   256
#define H_   64
#define E_   32
#define V_   29
#define G4   256   // 4*H

typedef unsigned long long ull;

// enc layout: stride 64, XOR-swizzled: logical (s, w) -> word s*64 + (w ^ ((4s)&63)).
// P1 row reads (LDS.128) and P3 column reads (LDS.32) both run at the bank floor.

struct __align__(16) Smem {
    float enc[S_ * 64];        // 65536 B
    float gate_emb[V_ * G4];   // 29696 B : W_ih[:, :32]@emb[v] + b_ih + b_hh
    float fcW[32 * 128];       // 16384 B (rows 29..31 unused)
    float embS[V_ * E_];       // prologue only
    float scores[S_];          // e_s (no max subtraction; |score| bounded)
    float part[16 * 64];       // context partials [q][hd]
    float gates[G4];
    float bias[G4];            // prologue only
    float comb[128];           // [0:64)=h  [64:128)=ctx  (fc input)
    float hdup[72];            // h halves at 0 / 40 (bank offset)
    float cdup[72];            // ctx halves at 0 / 40
    float fcb[32];
    float redsum[16];
    int   ytok[T_];
};

__device__ __forceinline__ ull pack2(float lo, float hi) {
    ull r; asm("mov.b64 %0, {%1, %2};" : "=l"(r) : "f"(lo), "f"(hi)); return r;
}
__device__ __forceinline__ ull fma2(ull a, ull b, ull c) {
    ull d; asm("fma.rn.f32x2 %0, %1, %2, %3;" : "=l"(d) : "l"(a), "l"(b), "l"(c));
    return d;
}
__device__ __forceinline__ float2 unpack2(ull v) {
    float lo, hi; asm("mov.b64 {%0, %1}, %2;" : "=f"(lo), "=f"(hi) : "l"(v));
    return make_float2(lo, hi);
}
__device__ __forceinline__ float sigmoid_(float z) {
    return 1.0f / (1.0f + __expf(-z));
}
__device__ __forceinline__ float tanh_(float x) {
    return 1.0f - 2.0f / (__expf(2.0f * x) + 1.0f);
}

extern "C" __global__ void __launch_bounds__(512, 1)
decoder_persist_kernel(const int* __restrict__ y,
                       const float* __restrict__ h0,
                       const float* __restrict__ c0,
                       const float* __restrict__ enc_g,
                       const float* __restrict__ embt,
                       const float* __restrict__ Wih,
                       const float* __restrict__ Whh,
                       const float* __restrict__ bih,
                       const float* __restrict__ bhh,
                       const float* __restrict__ fcWg,
                       const float* __restrict__ fcbg,
                       float* __restrict__ out)
{
    extern __shared__ __align__(16) char smem_raw[];
    Smem& sm = *reinterpret_cast<Smem*>(smem_raw);
    const int tid  = threadIdx.x;
    const int b    = blockIdx.x;
    const int lane = tid & 31;
    const int wrp  = tid >> 5;
    const int r    = tid >> 1;   // gate/score row
    const int half = tid & 1;

    // ---- per-thread gate weights (64 regs): ctx-slice + h-slice of row r ----
    // half h owns cols ctx[32h:32h+32) and h[32h:32h+32)
    ull wihc2[16], whh2[16];
    {
        const float4* wi = reinterpret_cast<const float4*>(Wih + r * 96 + 32 + 32 * half);
        #pragma unroll
        for (int k = 0; k < 8; k++) {
            float4 v = wi[k];
            wihc2[2*k]   = pack2(v.x, v.y);
            wihc2[2*k+1] = pack2(v.z, v.w);
        }
        const float4* wh = reinterpret_cast<const float4*>(Whh + r * 64 + 32 * half);
        #pragma unroll
        for (int k = 0; k < 8; k++) {
            float4 v = wh[k];
            whh2[2*k]   = pack2(v.x, v.y);
            whh2[2*k+1] = pack2(v.z, v.w);
        }
    }

    // ---- stage enc with XOR swizzle + constants ----
    {
        const float2* eb = reinterpret_cast<const float2*>(enc_g + (size_t)b * (S_ * H_));
        for (int i2 = tid; i2 < (S_ * H_) / 2; i2 += 512) {
            float2 v = eb[i2];
            int s = i2 >> 5;
            int w = (i2 & 31) << 1;                  // 0,2,...,62
            int dst = (s << 6) + (w ^ ((4 * s) & 63));
            *reinterpret_cast<float2*>(&sm.enc[dst]) = v;
        }
    }
    for (int i = tid; i < V_ * 128; i += 512) sm.fcW[i] = fcWg[i];
    for (int i = tid; i < V_ * E_;  i += 512) sm.embS[i] = embt[i];
    if (tid < G4) sm.bias[tid] = bih[tid] + bhh[tid];
    if (tid < V_) sm.fcb[tid]  = fcbg[tid];
    if (tid < T_) sm.ytok[tid] = y[b * T_ + tid];
    float creg = 0.0f;
    if (tid < H_) {
        float hv = h0[b * H_ + tid];
        sm.comb[tid] = hv;
        sm.hdup[tid + ((tid >> 5) << 3)] = hv;   // halves at 0 / 40
        creg = c0[b * H_ + tid];
    }
    __syncthreads();

    // ---- prologue: gate_emb[v][r] = W_ih[r, :32].emb[v] + bias[r] ----
    {
        float4 we[4];
        const float4* wg = reinterpret_cast<const float4*>(Wih + r * 96 + 16 * half);
        #pragma unroll
        for (int k = 0; k < 4; k++) we[k] = wg[k];
        float brow = sm.bias[r];
        for (int v = 0; v < V_; v++) {
            const float4* em = reinterpret_cast<const float4*>(sm.embS + v * E_ + 16 * half);
            float a = 0.f;
            #pragma unroll
            for (int k = 0; k < 4; k++) {
                float4 e = em[k];
                a += we[k].x*e.x + we[k].y*e.y + we[k].z*e.z + we[k].w*e.w;
            }
            a += __shfl_xor_sync(0xffffffffu, a, 1);
            if (half == 0) sm.gate_emb[v * G4 + r] = a + brow;
        }
    }
    __syncthreads();

    float* outp = out + (size_t)b * T_ * V_;

    for (int t = 0; t < T_; t++) {
        // ---- P1: e_s = exp(enc[s,:].h)  (2 threads/s, swizzled LDS.128) ----
        {
            const float4* hp4 = reinterpret_cast<const float4*>(sm.hdup + 40 * half);
            const int rot  = (4 * r) & 63;
            const int rowb = r << 6;
            ull a0 = 0ull, a1 = 0ull;
            #pragma unroll
            for (int j = 0; j < 8; j++) {
                int pw = rowb + (((half << 5) + (j << 2)) ^ rot);
                float4 ev = *reinterpret_cast<const float4*>(sm.enc + pw);
                float4 hv = hp4[j];
                a0 = fma2(pack2(ev.x, ev.y), pack2(hv.x, hv.y), a0);
                a1 = fma2(pack2(ev.z, ev.w), pack2(hv.z, hv.w), a1);
            }
            float2 fa = unpack2(a0), fb = unpack2(a1);
            float sc = (fa.x + fa.y) + (fb.x + fb.y);
            sc += __shfl_xor_sync(0xffffffffu, sc, 1);
            float e = __expf(sc);            // |sc| bounded: no overflow
            if (half == 0) sm.scores[r] = e;
            float su = e;
            #pragma unroll
            for (int o = 16; o > 1; o >>= 1)
                su += __shfl_xor_sync(0xffffffffu, su, o);
            // lane 0 = sum over even lanes = warp's 16 distinct scores, once each
            if (lane == 0) sm.redsum[wrp] = su;
        }
        // P3 consumes ONLY this warp's scores (sbase = wrp*16 = rows tid>>1 of
        // this warp) -> warp-level sync suffices; no block barrier.
        __syncwarp();

        // ---- P3: context partials; lane l owns hd = l and l+32 (swizzle, 1wf) ----
        {
            const int sbase = wrp * 16;
            float sc16[16];
            {
                const float4* sp = reinterpret_cast<const float4*>(sm.scores + sbase);
                #pragma unroll
                for (int k = 0; k < 4; k++) {
                    float4 v = sp[k];
                    sc16[4*k] = v.x; sc16[4*k+1] = v.y; sc16[4*k+2] = v.z; sc16[4*k+3] = v.w;
                }
            }
            float ax = 0.f, ay = 0.f;
            #pragma unroll
            for (int i = 0; i < 16; i++) {
                int s = sbase + i;
                const float* rowp = sm.enc + (s << 6);
                int w1 = lane ^ ((4 * s) & 63);
                ax += sc16[i] * rowp[w1];
                ay += sc16[i] * rowp[w1 ^ 32];
            }
            sm.part[wrp * 64 + lane]      = ax;   // hd = lane
            sm.part[wrp * 64 + lane + 32] = ay;   // hd = lane + 32
        }
        __syncthreads();  // bar_A: part, redsum

        // ---- ctx reduce + normalize -> comb[64:), cdup ----
        if (tid < H_) {
            float ssum = 0.f;
            #pragma unroll
            for (int k = 0; k < 16; k++) ssum += sm.redsum[k];
            float inv = 1.0f / ssum;
            float ctx = 0.f;
            #pragma unroll
            for (int q = 0; q < 16; q++) ctx += sm.part[q * 64 + tid];
            ctx *= inv;
            sm.comb[H_ + tid] = ctx;
            sm.cdup[tid + ((tid >> 5) << 3)] = ctx;   // halves at 0 / 40
        }
        __syncthreads();  // bar_B: ctx

        // ---- P4: gates = gate_emb[tok] + W_ihc@ctx + W_hh@h  (2 thr/row) ----
        {
            const float4* xp4 = reinterpret_cast<const float4*>(sm.cdup + 40 * half);
            const float4* hp4 = reinterpret_cast<const float4*>(sm.hdup + 40 * half);
            ull a0 = 0ull, a1 = 0ull;
            #pragma unroll
            for (int k = 0; k < 8; k++) {
                float4 xv = xp4[k];
                a0 = fma2(wihc2[2*k],   pack2(xv.x, xv.y), a0);
                a1 = fma2(wihc2[2*k+1], pack2(xv.z, xv.w), a1);
            }
            #pragma unroll
            for (int k = 0; k < 8; k++) {
                float4 hv = hp4[k];
                a0 = fma2(whh2[2*k],   pack2(hv.x, hv.y), a0);
                a1 = fma2(whh2[2*k+1], pack2(hv.z, hv.w), a1);
            }
            float2 fa = unpack2(a0), fb = unpack2(a1);
            float g = (fa.x + fa.y) + (fb.x + fb.y);
            g += __shfl_xor_sync(0xffffffffu, g, 1);
            if (half == 0)
                sm.gates[r] = g + sm.gate_emb[sm.ytok[t] * G4 + r];
        }
        __syncthreads();  // bar_C: gates

        // ---- P5: LSTM cell (torch order i,f,g,o) ----
        if (tid < H_) {
            float ig = sm.gates[tid];
            float fg = sm.gates[H_ + tid];
            float gg = sm.gates[2 * H_ + tid];
            float og = sm.gates[3 * H_ + tid];
            creg = sigmoid_(fg) * creg + sigmoid_(ig) * tanh_(gg);
            float hnew = sigmoid_(og) * tanh_(creg);
            sm.comb[tid] = hnew;
            sm.hdup[tid + ((tid >> 5) << 3)] = hnew;
        }
        __syncthreads();  // bar_D: h

        // ---- P6: logits (16 threads per vocab row) ----
        {
            int v = tid >> 4, p = tid & 15;
            float acc = 0.0f;
            if (v < V_) {
                const float4* fw = reinterpret_cast<const float4*>(sm.fcW + v * 128 + p * 8);
                const float4* cb = reinterpret_cast<const float4*>(sm.comb + p * 8);
                float4 w0 = fw[0], w1 = fw[1];
                float4 c0v = cb[0], c1v = cb[1];
                acc = w0.x*c0v.x + w0.y*c0v.y + w0.z*c0v.z + w0.w*c0v.w
                    + w1.x*c1v.x + w1.y*c1v.y + w1.z*c1v.z + w1.w*c1v.w;
            }
            #pragma unroll
            for (int o = 8; o; o >>= 1)
                acc += __shfl_xor_sync(0xffffffffu, acc, o);
            if (p == 0 && v < V_)
                outp[t * V_ + v] = acc + sm.fcb[v];
        }
        // no trailing barrier: every buffer P6 reads (comb, fcW) is next
        // written only after >=1 subsequent block barrier of step t+1.
    }
}

extern "C" void kernel_launch(void* const* d_in, const int* in_sizes, int n_in,
                              void* d_out, int out_size) {
    const int*   y    = (const int*)d_in[0];
    const float* h0   = (const float*)d_in[1];
    const float* c0   = (const float*)d_in[2];
    const float* enc  = (const float*)d_in[3];
    const float* emb  = (const float*)d_in[4];
    const float* Wih  = (const float*)d_in[5];
    const float* Whh  = (const float*)d_in[6];
    const float* bih  = (const float*)d_in[7];
    const float* bhh  = (const float*)d_in[8];
    const float* fcW  = (const float*)d_in[9];
    const float* fcb  = (const float*)d_in[10];
    float* out = (float*)d_out;

    size_t smem = sizeof(Smem);
    cudaFuncSetAttribute(decoder_persist_kernel,
                         cudaFuncAttributeMaxDynamicSharedMemorySize, (int)smem);
    decoder_persist_kernel<<<B_, 512, smem>>>(y, h0, c0, enc, emb,
                                              Wih, Whh, bih, bhh, fcW, fcb, out);
}

// round 16
// speedup vs baseline: 1.5315x; 1.3181x over previous
#include <cuda_runtime.h>

#define B_   2048
#define T_   128
#define S_   256
#define H_   64
#define E_   32
#define V_   29
#define G4   256   // 4*H
#define ES   68    // enc SMEM row stride; halves at +0 and +34 (conflict-free)

typedef unsigned long long ull;

struct __align__(16) Smem {
    float enc0[S_ * ES];       // 69632 B
    float enc1[S_ * ES];       // 69632 B
    float gate_emb[V_ * G4];   // 29696 B : W_ih[:, :32]@emb[v] + b_ih + b_hh
    float fcW[32 * 128];       // 16384 B (rows 29..31 unused)
    float embS[V_ * E_];       // prologue only
    float scores0[S_], scores1[S_];
    float part0[16 * 64], part1[16 * 64];
    float gates0[G4], gates1[G4];
    float bias[G4];            // prologue only
    float comb0[128], comb1[128];   // [0:64)=h [64:128)=ctx
    float hdup0[72], hdup1[72];     // h halves at 0 / 40 (bank offset)
    float cdup0[72], cdup1[72];     // ctx halves at 0 / 40
    float fcb[32];
    float redsum0[16], redsum1[16];
    int   ytok0[T_], ytok1[T_];
};

__device__ __forceinline__ ull pack2(float lo, float hi) {
    ull r; asm("mov.b64 %0, {%1, %2};" : "=l"(r) : "f"(lo), "f"(hi)); return r;
}
__device__ __forceinline__ ull fma2(ull a, ull b, ull c) {
    ull d; asm("fma.rn.f32x2 %0, %1, %2, %3;" : "=l"(d) : "l"(a), "l"(b), "l"(c));
    return d;
}
__device__ __forceinline__ float2 unpack2(ull v) {
    float lo, hi; asm("mov.b64 {%0, %1}, %2;" : "=f"(lo), "=f"(hi) : "l"(v));
    return make_float2(lo, hi);
}
__device__ __forceinline__ float sigmoid_(float z) {
    return 1.0f / (1.0f + __expf(-z));
}
__device__ __forceinline__ float tanh_(float x) {
    return 1.0f - 2.0f / (__expf(2.0f * x) + 1.0f);
}

// ---- P1: e_s = exp(enc[s,:].h), 2 threads/s, mid-pad layout (R3-verified) ----
__device__ __forceinline__ void phase1(const float* __restrict__ enc,
                                       const float* __restrict__ hdup,
                                       float* __restrict__ scores,
                                       float* __restrict__ redsum,
                                       int r, int half, int lane, int wrp)
{
    const ull* ep = reinterpret_cast<const ull*>(enc + r * ES + half * 34);
    const ull* hp = reinterpret_cast<const ull*>(hdup + half * 40);
    ull a0 = 0ull, a1 = 0ull;
    #pragma unroll
    for (int k = 0; k < 16; k += 2) {
        a0 = fma2(ep[k],     hp[k],     a0);
        a1 = fma2(ep[k + 1], hp[k + 1], a1);
    }
    float2 fa = unpack2(a0), fb = unpack2(a1);
    float sc = (fa.x + fa.y) + (fb.x + fb.y);
    sc += __shfl_xor_sync(0xffffffffu, sc, 1);
    float e = __expf(sc);                   // |sc| bounded: no overflow
    if (half == 0) scores[r] = e;
    float su = e;
    #pragma unroll
    for (int o = 16; o > 1; o >>= 1)
        su += __shfl_xor_sync(0xffffffffu, su, o);
    // lane 0 = sum over even lanes = warp's 16 distinct scores, once each
    if (lane == 0) redsum[wrp] = su;
}

// ---- P3: context partials, warp q handles 16 s-rows (R3-verified) ----
__device__ __forceinline__ void phase3(const float* __restrict__ enc,
                                       const float* __restrict__ scores,
                                       float* __restrict__ part,
                                       int wrp, int lane)
{
    const int sbase = wrp * 16;
    const float*  ebase = enc + sbase * ES + 2 * lane + ((lane >> 4) & 1) * 2;
    const float4* sp = reinterpret_cast<const float4*>(scores + sbase);
    float ax = 0.f, ay = 0.f;
    #pragma unroll
    for (int c = 0; c < 4; c++) {
        float4 sv = sp[c];
        float2 e0 = *reinterpret_cast<const float2*>(ebase + (4*c + 0) * ES);
        float2 e1 = *reinterpret_cast<const float2*>(ebase + (4*c + 1) * ES);
        float2 e2 = *reinterpret_cast<const float2*>(ebase + (4*c + 2) * ES);
        float2 e3 = *reinterpret_cast<const float2*>(ebase + (4*c + 3) * ES);
        ax += sv.x * e0.x; ay += sv.x * e0.y;
        ax += sv.y * e1.x; ay += sv.y * e1.y;
        ax += sv.z * e2.x; ay += sv.z * e2.y;
        ax += sv.w * e3.x; ay += sv.w * e3.y;
    }
    *reinterpret_cast<float2*>(&part[wrp * 64 + 2 * lane]) = make_float2(ax, ay);
}

// ---- ctx reduce + normalize (R3-verified) ----
__device__ __forceinline__ void ctx_reduce(const float* __restrict__ redsum,
                                           const float* __restrict__ part,
                                           float* __restrict__ comb,
                                           float* __restrict__ cdup, int j)
{
    float ssum = 0.f;
    #pragma unroll
    for (int k = 0; k < 16; k++) ssum += redsum[k];
    float inv = 1.0f / ssum;
    float ctx = 0.f;
    #pragma unroll
    for (int q = 0; q < 16; q++) ctx += part[q * 64 + j];
    ctx *= inv;
    comb[H_ + j] = ctx;
    cdup[j + ((j >> 5) << 3)] = ctx;   // halves at 0 / 40
}

// ---- P4: gates = gate_emb[tok] + W_ihc@ctx + W_hh@h (R14-verified fold) ----
__device__ __forceinline__ void phase4(const float* __restrict__ cdup,
                                       const float* __restrict__ hdup,
                                       const float* __restrict__ ge,
                                       float* __restrict__ gates,
                                       const ull* __restrict__ wihc2,
                                       const ull* __restrict__ whh2,
                                       int r, int half)
{
    const float4* xp4 = reinterpret_cast<const float4*>(cdup + 40 * half);
    const float4* hp4 = reinterpret_cast<const float4*>(hdup + 40 * half);
    ull a0 = 0ull, a1 = 0ull;
    #pragma unroll
    for (int k = 0; k < 8; k++) {
        float4 xv = xp4[k];
        a0 = fma2(wihc2[2*k],   pack2(xv.x, xv.y), a0);
        a1 = fma2(wihc2[2*k+1], pack2(xv.z, xv.w), a1);
    }
    #pragma unroll
    for (int k = 0; k < 8; k++) {
        float4 hv = hp4[k];
        a0 = fma2(whh2[2*k],   pack2(hv.x, hv.y), a0);
        a1 = fma2(whh2[2*k+1], pack2(hv.z, hv.w), a1);
    }
    float2 fa = unpack2(a0), fb = unpack2(a1);
    float g = (fa.x + fa.y) + (fb.x + fb.y);
    g += __shfl_xor_sync(0xffffffffu, g, 1);
    if (half == 0) gates[r] = g + ge[r];
}

// ---- P5: LSTM cell (torch order i,f,g,o) ----
__device__ __forceinline__ float lstm_cell(const float* __restrict__ gates,
                                           float c,
                                           float* __restrict__ comb,
                                           float* __restrict__ hdup, int j)
{
    float ig = gates[j];
    float fg = gates[H_ + j];
    float gg = gates[2 * H_ + j];
    float og = gates[3 * H_ + j];
    c = sigmoid_(fg) * c + sigmoid_(ig) * tanh_(gg);
    float hn = sigmoid_(og) * tanh_(c);
    comb[j] = hn;
    hdup[j + ((j >> 5) << 3)] = hn;
    return c;
}

// ---- P6: logits, 16 threads per vocab row (R3-verified) ----
__device__ __forceinline__ void phase6(const float* __restrict__ fcW,
                                       const float* __restrict__ comb,
                                       const float* __restrict__ fcb,
                                       float* __restrict__ outp_t, int tid)
{
    int v = tid >> 4, p = tid & 15;
    float acc = 0.0f;
    if (v < V_) {
        const float4* fw = reinterpret_cast<const float4*>(fcW + v * 128 + p * 8);
        const float4* cb = reinterpret_cast<const float4*>(comb + p * 8);
        float4 w0 = fw[0], w1 = fw[1];
        float4 c0v = cb[0], c1v = cb[1];
        acc = w0.x*c0v.x + w0.y*c0v.y + w0.z*c0v.z + w0.w*c0v.w
            + w1.x*c1v.x + w1.y*c1v.y + w1.z*c1v.z + w1.w*c1v.w;
    }
    #pragma unroll
    for (int o = 8; o; o >>= 1)
        acc += __shfl_xor_sync(0xffffffffu, acc, o);
    if (p == 0 && v < V_)
        outp_t[v] = acc + fcb[v];
}

extern "C" __global__ void __launch_bounds__(512, 1)
decoder_persist_kernel(const int* __restrict__ y,
                       const float* __restrict__ h0,
                       const float* __restrict__ c0,
                       const float* __restrict__ enc_g,
                       const float* __restrict__ embt,
                       const float* __restrict__ Wih,
                       const float* __restrict__ Whh,
                       const float* __restrict__ bih,
                       const float* __restrict__ bhh,
                       const float* __restrict__ fcWg,
                       const float* __restrict__ fcbg,
                       float* __restrict__ out)
{
    extern __shared__ __align__(16) char smem_raw[];
    Smem& sm = *reinterpret_cast<Smem*>(smem_raw);
    const int tid  = threadIdx.x;
    const int b0   = 2 * blockIdx.x;
    const int b1   = b0 + 1;
    const int lane = tid & 31;
    const int wrp  = tid >> 5;
    const int r    = tid >> 1;
    const int half = tid & 1;

    // ---- per-thread gate weights (64 regs), shared by both batches ----
    ull wihc2[16], whh2[16];
    {
        const float4* wi = reinterpret_cast<const float4*>(Wih + r * 96 + 32 + 32 * half);
        #pragma unroll
        for (int k = 0; k < 8; k++) {
            float4 v = wi[k];
            wihc2[2*k]   = pack2(v.x, v.y);
            wihc2[2*k+1] = pack2(v.z, v.w);
        }
        const float4* wh = reinterpret_cast<const float4*>(Whh + r * 64 + 32 * half);
        #pragma unroll
        for (int k = 0; k < 8; k++) {
            float4 v = wh[k];
            whh2[2*k]   = pack2(v.x, v.y);
            whh2[2*k+1] = pack2(v.z, v.w);
        }
    }

    // ---- stage both enc slices (mid-row pad layout) + constants ----
    {
        const float2* e0 = reinterpret_cast<const float2*>(enc_g + (size_t)b0 * (S_ * H_));
        const float2* e1 = reinterpret_cast<const float2*>(enc_g + (size_t)b1 * (S_ * H_));
        for (int i2 = tid; i2 < (S_ * H_) / 2; i2 += 512) {
            int s  = i2 >> 5;
            int h2 = (i2 & 31) << 1;
            int dst = s * ES + h2 + ((h2 >= 32) ? 2 : 0);
            *reinterpret_cast<float2*>(&sm.enc0[dst]) = e0[i2];
            *reinterpret_cast<float2*>(&sm.enc1[dst]) = e1[i2];
        }
    }
    for (int i = tid; i < V_ * 128; i += 512) sm.fcW[i] = fcWg[i];
    for (int i = tid; i < V_ * E_;  i += 512) sm.embS[i] = embt[i];
    if (tid < G4) sm.bias[tid] = bih[tid] + bhh[tid];
    if (tid < V_) sm.fcb[tid]  = fcbg[tid];
    if (tid < T_) { sm.ytok0[tid] = y[b0 * T_ + tid]; sm.ytok1[tid] = y[b1 * T_ + tid]; }
    float creg = 0.0f;
    if (tid < H_) {
        float hv = h0[b0 * H_ + tid];
        sm.comb0[tid] = hv;
        sm.hdup0[tid + ((tid >> 5) << 3)] = hv;
        creg = c0[b0 * H_ + tid];
    } else if (tid < 2 * H_) {
        int j = tid - H_;
        float hv = h0[b1 * H_ + j];
        sm.comb1[j] = hv;
        sm.hdup1[j + ((j >> 5) << 3)] = hv;
        creg = c0[b1 * H_ + j];
    }
    __syncthreads();

    // ---- prologue: gate_emb[v][r] = W_ih[r, :32].emb[v] + bias[r] ----
    {
        float4 we[4];
        const float4* wg = reinterpret_cast<const float4*>(Wih + r * 96 + 16 * half);
        #pragma unroll
        for (int k = 0; k < 4; k++) we[k] = wg[k];
        float brow = sm.bias[r];
        for (int v = 0; v < V_; v++) {
            const float4* em = reinterpret_cast<const float4*>(sm.embS + v * E_ + 16 * half);
            float a = 0.f;
            #pragma unroll
            for (int k = 0; k < 4; k++) {
                float4 e = em[k];
                a += we[k].x*e.x + we[k].y*e.y + we[k].z*e.z + we[k].w*e.w;
            }
            a += __shfl_xor_sync(0xffffffffu, a, 1);
            if (half == 0) sm.gate_emb[v * G4 + r] = a + brow;
        }
    }
    __syncthreads();

    float* outp0 = out + (size_t)b0 * T_ * V_;
    float* outp1 = out + (size_t)b1 * T_ * V_;

    for (int t = 0; t < T_; t++) {
        // ---- region 1: P1 + P3 for both batches (P3 is same-warp-only) ----
        phase1(sm.enc0, sm.hdup0, sm.scores0, sm.redsum0, r, half, lane, wrp);
        phase1(sm.enc1, sm.hdup1, sm.scores1, sm.redsum1, r, half, lane, wrp);
        __syncwarp();
        phase3(sm.enc0, sm.scores0, sm.part0, wrp, lane);
        phase3(sm.enc1, sm.scores1, sm.part1, wrp, lane);
        __syncthreads();  // bar_A: part*, redsum*

        // ---- region 2: ctx reduce, both batches in parallel ----
        if (tid < H_)
            ctx_reduce(sm.redsum0, sm.part0, sm.comb0, sm.cdup0, tid);
        else if (tid < 2 * H_)
            ctx_reduce(sm.redsum1, sm.part1, sm.comb1, sm.cdup1, tid - H_);
        __syncthreads();  // bar_B: ctx*

        // ---- region 3: P4 for both batches ----
        phase4(sm.cdup0, sm.hdup0, sm.gate_emb + sm.ytok0[t] * G4, sm.gates0,
               wihc2, whh2, r, half);
        phase4(sm.cdup1, sm.hdup1, sm.gate_emb + sm.ytok1[t] * G4, sm.gates1,
               wihc2, whh2, r, half);
        __syncthreads();  // bar_C: gates*

        // ---- region 4: LSTM cells, both batches in parallel ----
        if (tid < H_)
            creg = lstm_cell(sm.gates0, creg, sm.comb0, sm.hdup0, tid);
        else if (tid < 2 * H_)
            creg = lstm_cell(sm.gates1, creg, sm.comb1, sm.hdup1, tid - H_);
        __syncthreads();  // bar_D: h*

        // ---- region 5: P6 logits for both batches ----
        phase6(sm.fcW, sm.comb0, sm.fcb, outp0 + t * V_, tid);
        phase6(sm.fcW, sm.comb1, sm.fcb, outp1 + t * V_, tid);
        // no trailing barrier: comb*/hdup* are next written in regions 2/4 of
        // step t+1, each behind >=1 block barrier that all warps (hence all
        // finished P6s) must reach first.
    }
}

extern "C" void kernel_launch(void* const* d_in, const int* in_sizes, int n_in,
                              void* d_out, int out_size) {
    const int*   y    = (const int*)d_in[0];
    const float* h0   = (const float*)d_in[1];
    const float* c0   = (const float*)d_in[2];
    const float* enc  = (const float*)d_in[3];
    const float* emb  = (const float*)d_in[4];
    const float* Wih  = (const float*)d_in[5];
    const float* Whh  = (const float*)d_in[6];
    const float* bih  = (const float*)d_in[7];
    const float* bhh  = (const float*)d_in[8];
    const float* fcW  = (const float*)d_in[9];
    const float* fcb  = (const float*)d_in[10];
    float* out = (float*)d_out;

    size_t smem = sizeof(Smem);
    cudaFuncSetAttribute(decoder_persist_kernel,
                         cudaFuncAttributeMaxDynamicSharedMemorySize, (int)smem);
    decoder_persist_kernel<<<B_ / 2, 512, smem>>>(y, h0, c0, enc, emb,
                                                  Wih, Whh, bih, bhh, fcW, fcb, out);
}